// round 11
// baseline (speedup 1.0000x reference)
#include <cuda_runtime.h>
#include <cuda_fp16.h>
#include <cstdint>

// Problem constants
#define BB 16
#define NN 4096
#define MM 1024
#define KK 32
#define FF 128

// out[b,m,f] = max_k inputs[b, idx[b,m,k], f]
//
// R6-R9 lesson: L2-gather plateaus ~18.5us because random indices amplify
// table reads 4x (128 MB fp16 through L2 at ~10-12 TB/s) + 4.4us convert.
// R10: per-(batch, 16-feature-tile) block caches its [4096 x 16] fp16 slice
// in SMEM (once, fused fp32->fp16), then serves all 1024 rows from SMEM.
// Global traffic drops to compulsory (~56 MB); the amplified 128 MB moves to
// the smem crossbar (~33 TB/s aggregate). Row stride padded to 9 half2 (36B)
// so bank spans start at 9t mod 32 (odd multiplier -> uniform spread).

#define FT        16            // halfs per feature tile
#define RSTRIDE   9             // half2 per smem row (8 data + 1 pad)
#define THREADS   512
#define WARPS     (THREADS / 32)
#define SMEM_BYTES (NN * RSTRIDE * 4)   // 4096*9*4 = 147456 B

__global__ void gmp_kernel(const float* __restrict__ inputs,
                           const int*   __restrict__ batch_index,
                           float*       __restrict__ out)
{
    extern __shared__ __half2 stab[];    // [NN * RSTRIDE]

    const int bid  = blockIdx.x;
    const int b    = bid >> 3;           // batch       (128 blocks = 16 x 8)
    const int ft   = bid & 7;            // feature tile
    const int tid  = threadIdx.x;
    const int lane = tid & 31;
    const int w    = tid >> 5;
    const int c    = lane & 7;           // half2 column within tile (0..7)
    const int g    = lane >> 3;          // m-group within warp (0..3)

    // ---- Phase 1: load + convert this block's [NN, FT] slice into SMEM ----
    {
        // Row n, half2 col cc lives at inputs[b][n][ft*16 + 2cc] (float2).
        const float2* src = (const float2*)(inputs + (size_t)b * (NN * FF) + ft * FT);
        #pragma unroll
        for (int i = 0; i < (NN * 8) / THREADS; ++i) {   // 64 iterations
            const int s  = tid + i * THREADS;
            const int n  = s >> 3;
            const int cc = s & 7;
            const float2 f = __ldg(&src[(size_t)n * (FF / 2) + cc]);
            stab[n * RSTRIDE + cc] = __floats2half2_rn(f.x, f.y);
        }
    }
    __syncthreads();

    // -inf is the max identity; table entries are finite so result is finite.
    const __half2 NEGH = __floats2half2_rn(-3.402823466e+38f, -3.402823466e+38f);
    const int* idxb = batch_index + (size_t)b * (MM * KK);

    // ---- Phase 2: gather-max from SMEM. 4 rows per warp, 16 iterations. ----
    #pragma unroll 1
    for (int iter = 0; iter < MM / (WARPS * 4); ++iter) {
        const int m = iter * (WARPS * 4) + w * 4 + g;

        // Lane holds int4 #c of row m's 32 indices (k = 4c .. 4c+3).
        // Warp loads 4 rows x 128B = 512B fully coalesced.
        const int4 raw = __ldg((const int4*)(idxb + (size_t)m * KK) + c);
        int r0 = raw.x & (NN - 1);   // identity on valid data; OOB-proof
        int r1 = raw.y & (NN - 1);
        int r2 = raw.z & (NN - 1);
        int r3 = raw.w & (NN - 1);

        __half2 acc = NEGH;
        #pragma unroll
        for (int k = 0; k < KK; ++k) {
            // Broadcast index k within the 8-lane group: source lane k>>2,
            // component k&3 (compile-time after unroll).
            int v;
            switch (k & 3) {
                case 0: v = r0; break;
                case 1: v = r1; break;
                case 2: v = r2; break;
                default: v = r3; break;
            }
            const int t = __shfl_sync(0xffffffffu, v, k >> 2, 8);
            acc = __hmax2(acc, stab[t * RSTRIDE + c]);
        }

        // Lane writes its 2 features of row m: group = 64B contiguous.
        float2* orow = (float2*)(out + (size_t)b * (MM * FF) + (size_t)m * FF + ft * FT);
        const float2 f = __half22float2(acc);
        __stcs(&orow[c], f);
    }
}

extern "C" void kernel_launch(void* const* d_in, const int* in_sizes, int n_in,
                              void* d_out, int out_size)
{
    // Identify inputs by element count:
    //   inputs:      16*4096*128 = 8388608 (f32)
    //   batch_index: 16*1024*32  =  524288 (i32)
    const float* inputs;
    const int*   batch_index;
    if (in_sizes[0] == BB * NN * FF) {
        inputs      = (const float*)d_in[0];
        batch_index = (const int*)d_in[1];
    } else {
        inputs      = (const float*)d_in[1];
        batch_index = (const int*)d_in[0];
    }
    float* out = (float*)d_out;

    // 147456 B dynamic smem > 48KB default: opt in (idempotent, host-side).
    cudaFuncSetAttribute(gmp_kernel,
                         cudaFuncAttributeMaxDynamicSharedMemorySize, SMEM_BYTES);

    // One block per (batch, feature-tile): 16 * 8 = 128 blocks, 512 threads.
    gmp_kernel<<<BB * (FF / FT), THREADS, SMEM_BYTES>>>(inputs, batch_index, out);
}